// round 11
// baseline (speedup 1.0000x reference)
#include <cuda_runtime.h>
#include <cuda_bf16.h>
#include <math.h>
#include <stdint.h>

#define N_TOK 16384
#define C_DIM 768
#define I_DIM 1536
#define E_EXP 16
#define E_ALL 17
#define SLOTS (3*N_TOK)
#define TILE_B 16384
#define STAGE_FI 65536
#define STAGE_D (4*TILE_B)
#define SMEM_FI (2*STAGE_FI + 1024)
#define SMEM_D  (2*STAGE_D + 1024)

// ---------------- static device scratch ----------------
__device__ int   g_counts[E_EXP];
__device__ int   g_offsets[E_EXP];
__device__ int   g_cursor[E_EXP];
__device__ int   g_re[N_TOK*2];
__device__ float g_rw[N_TOK*2];
__device__ int   g_ids[SLOTS];
__device__ float g_wt[SLOTS];
__device__ int   g_slot_of[N_TOK*2];

__device__ signed char g_x1[(size_t)N_TOK*C_DIM];
__device__ signed char g_x0[(size_t)N_TOK*C_DIM];
__device__ signed char g_wg1[(size_t)E_ALL*I_DIM*C_DIM];  // [(e*I+n)*C+k]
__device__ signed char g_wg0[(size_t)E_ALL*I_DIM*C_DIM];
__device__ signed char g_wu1[(size_t)E_ALL*I_DIM*C_DIM];
__device__ signed char g_wu0[(size_t)E_ALL*I_DIM*C_DIM];
__device__ float g_sx[N_TOK];
__device__ float g_sg[E_ALL*I_DIM];
__device__ float g_su[E_ALL*I_DIM];
__device__ __nv_bfloat16 g_dh[(size_t)E_ALL*C_DIM*I_DIM]; // [(e*C+n)*I+k]
__device__ __nv_bfloat16 g_dl[(size_t)E_ALL*C_DIM*I_DIM];
__device__ __nv_bfloat16 g_hh[(size_t)SLOTS*I_DIM];
__device__ __nv_bfloat16 g_hl[(size_t)SLOTS*I_DIM];
__device__ float g_O[(size_t)SLOTS*C_DIM];

// ---------------- PTX helpers (base ISA only) ----------------
__device__ __forceinline__ uint32_t smem_u32(const void* p){
    uint32_t a;
    asm("{ .reg .u64 t; cvta.to.shared.u64 t, %1; cvt.u32.u64 %0, t; }" : "=r"(a) : "l"(p));
    return a;
}
__device__ __forceinline__ void cp_row(uint32_t sbase, const void* src, int t){
    #pragma unroll
    for (int ch = 0; ch < 8; ch++){
        uint32_t off = (uint32_t)t*128u + (uint32_t)ch*16u;
        uint32_t dst = sbase + (off ^ ((off >> 3) & 0x70u));
        asm volatile("cp.async.cg.shared.global [%0], [%1], 16;"
            :: "r"(dst), "l"((const char*)src + ch*16) : "memory");
    }
}
__device__ __forceinline__ void cp_commit(){ asm volatile("cp.async.commit_group;" ::: "memory"); }
__device__ __forceinline__ void cp_wait1(){ asm volatile("cp.async.wait_group 1;" ::: "memory"); }
__device__ __forceinline__ void cp_wait0(){ asm volatile("cp.async.wait_group 0;" ::: "memory"); }

__device__ __forceinline__ void ldsm4(uint32_t* r, uint32_t addr){
    asm volatile("ldmatrix.sync.aligned.m8n8.x4.shared.b16 {%0,%1,%2,%3}, [%4];"
        : "=r"(r[0]), "=r"(r[1]), "=r"(r[2]), "=r"(r[3]) : "r"(addr));
}
__device__ __forceinline__ void hmma(float* d, const uint32_t* a, const uint32_t* b){
    asm volatile("mma.sync.aligned.m16n8k16.row.col.f32.bf16.bf16.f32 "
        "{%0,%1,%2,%3}, {%4,%5,%6,%7}, {%8,%9}, {%0,%1,%2,%3};"
        : "+f"(d[0]), "+f"(d[1]), "+f"(d[2]), "+f"(d[3])
        : "r"(a[0]), "r"(a[1]), "r"(a[2]), "r"(a[3]), "r"(b[0]), "r"(b[1]));
}
__device__ __forceinline__ void imma(int* d, const uint32_t* a, uint32_t b0, uint32_t b1){
    asm volatile("mma.sync.aligned.m16n8k32.row.col.s32.s8.s8.s32 "
        "{%0,%1,%2,%3}, {%4,%5,%6,%7}, {%8,%9}, {%0,%1,%2,%3};"
        : "+r"(d[0]), "+r"(d[1]), "+r"(d[2]), "+r"(d[3])
        : "r"(a[0]), "r"(a[1]), "r"(a[2]), "r"(a[3]), "r"(b0), "r"(b1));
}

// ---------------- routing setup ----------------
__global__ void init_kernel(){ if (threadIdx.x < E_EXP) g_counts[threadIdx.x] = 0; }

__global__ void router_kernel(const float* __restrict__ x, const float* __restrict__ wgate,
                              const float* __restrict__ bias){
    int warp = (blockIdx.x * blockDim.x + threadIdx.x) >> 5;
    int lane = threadIdx.x & 31;
    if (warp >= N_TOK) return;
    float acc = 0.f;
    if (lane < E_EXP){
        const float* xr = x + (size_t)warp * C_DIM;
        #pragma unroll 8
        for (int c = 0; c < C_DIM; c++) acc = fmaf(xr[c], wgate[c*E_EXP + lane], acc);
        acc += bias[lane];
    }
    float l0 = -1e30f, l1 = -1e30f; int i0 = 0, i1 = 0;
    #pragma unroll
    for (int e = 0; e < E_EXP; e++){
        float v = __shfl_sync(0xffffffffu, acc, e);
        if (v > l0)      { l1 = l0; i1 = i0; l0 = v; i0 = e; }
        else if (v > l1) { l1 = v;  i1 = e; }
    }
    if (lane == 0){
        float w0 = 1.f / (1.f + __expf(l1 - l0));
        g_re[warp*2+0] = i0; g_rw[warp*2+0] = w0;
        g_re[warp*2+1] = i1; g_rw[warp*2+1] = 1.f - w0;
        atomicAdd(&g_counts[i0], 1); atomicAdd(&g_counts[i1], 1);
    }
}

__global__ void scan_kernel(){
    if (threadIdx.x == 0){
        int off = 0;
        for (int e = 0; e < E_EXP; e++){ g_offsets[e] = off; g_cursor[e] = off; off += g_counts[e]; }
    }
}

__global__ void fill_kernel(){
    int t = blockIdx.x * blockDim.x + threadIdx.x;
    if (t >= N_TOK) return;
    #pragma unroll
    for (int s = 0; s < 2; s++){
        int e = g_re[t*2+s];
        int pos = atomicAdd(&g_cursor[e], 1);
        g_ids[pos] = t; g_wt[pos] = g_rw[t*2+s]; g_slot_of[t*2+s] = pos;
    }
    g_ids[2*N_TOK + t] = t; g_wt[2*N_TOK + t] = 1.f;
}

// ---------------- quantization (x, wg, wu) ----------------
__device__ __forceinline__ void q2(float v, float inv, signed char& q1, signed char& q0){
    float q = v * inv;
    q = fminf(127.f, fmaxf(-127.f, q));
    int i1 = __float2int_rn(q);
    int i0 = __float2int_rn(128.f * (q - (float)i1));
    q1 = (signed char)i1; q0 = (signed char)i0;
}

__global__ void rowmax_x_kernel(const float* __restrict__ x){
    int t = (blockIdx.x * blockDim.x + threadIdx.x) >> 5;
    int lane = threadIdx.x & 31;
    if (t >= N_TOK) return;
    float m = 0.f;
    for (int c = lane; c < C_DIM; c += 32) m = fmaxf(m, fabsf(x[(size_t)t*C_DIM + c]));
    #pragma unroll
    for (int o = 16; o > 0; o >>= 1) m = fmaxf(m, __shfl_xor_sync(0xffffffffu, m, o));
    if (lane == 0) g_sx[t] = m * (1.f/127.f);
}

__global__ void quant_x_kernel(const float* __restrict__ x){
    size_t base = ((size_t)blockIdx.x * blockDim.x + threadIdx.x) * 4;
    if (base >= (size_t)N_TOK*C_DIM) return;
    int t = (int)(base / C_DIM);
    float s = g_sx[t];
    float inv = s > 0.f ? 1.f/s : 0.f;
    float4 v = *(const float4*)(x + base);
    char4 a, b;
    q2(v.x, inv, a.x, b.x); q2(v.y, inv, a.y, b.y);
    q2(v.z, inv, a.z, b.z); q2(v.w, inv, a.w, b.w);
    *(char4*)(g_x1 + base) = a;
    *(char4*)(g_x0 + base) = b;
}

// NOTE: outputs selected DEVICE-SIDE via `which` — device-global symbols must
// never be passed as kernel arguments from host code (R9/R10 root cause).
__global__ void colmax_w_kernel(const float* __restrict__ W, int which,
                                int ebase, int K, int N){
    float* sArr = (which == 0) ? g_sg : g_su;
    int e = ebase + blockIdx.z;
    const float* Win = W + (size_t)blockIdx.z * K * N;
    int n = blockIdx.x * blockDim.x + threadIdx.x;
    if (n >= N) return;
    float m = 0.f;
    for (int k = 0; k < K; k++) m = fmaxf(m, fabsf(Win[(size_t)k*N + n]));
    sArr[e*N + n] = m * (1.f/127.f);
}

__global__ void quantT_w_kernel(const float* __restrict__ W, int which,
                                int ebase, int K, int N){
    signed char* q1p = (which == 0) ? g_wg1 : g_wu1;
    signed char* q0p = (which == 0) ? g_wg0 : g_wu0;
    const float* sArr = (which == 0) ? g_sg : g_su;
    __shared__ float t[32][33];
    int e = ebase + blockIdx.z;
    const float* Win = W + (size_t)blockIdx.z * K * N;
    int n0 = blockIdx.x*32, k0 = blockIdx.y*32;
    int tx = threadIdx.x, ty = threadIdx.y;   // (32,8)
    #pragma unroll
    for (int i = 0; i < 4; i++)
        t[ty + i*8][tx] = Win[(size_t)(k0 + ty + i*8)*N + n0 + tx];
    __syncthreads();
    #pragma unroll
    for (int i = 0; i < 4; i++){
        int n = n0 + ty + i*8;
        float v = t[tx][ty + i*8];
        float s = sArr[e*N + n];
        float inv = s > 0.f ? 1.f/s : 0.f;
        signed char a, b; q2(v, inv, a, b);
        size_t o = ((size_t)e*N + n)*K + k0 + tx;
        q1p[o] = a; q0p[o] = b;
    }
}

// split + transpose wd (bf16 hi/lo): W (K,N) -> [(e*N+n)*K+k]
__global__ void split_T_wd_kernel(const float* __restrict__ W, int ebase, int K, int N){
    __shared__ float t[32][33];
    int e = ebase + blockIdx.z;
    const float* Win = W + (size_t)blockIdx.z * K * N;
    int n0 = blockIdx.x*32, k0 = blockIdx.y*32;
    int tx = threadIdx.x, ty = threadIdx.y;   // (32,8)
    #pragma unroll
    for (int i = 0; i < 4; i++)
        t[ty + i*8][tx] = Win[(size_t)(k0 + ty + i*8)*N + n0 + tx];
    __syncthreads();
    #pragma unroll
    for (int i = 0; i < 4; i++){
        int n = n0 + ty + i*8;
        float v = t[tx][ty + i*8];
        size_t o = ((size_t)e*N + n)*K + k0 + tx;
        __nv_bfloat16 h = __float2bfloat16(v);
        g_dh[o] = h; g_dl[o] = __float2bfloat16(v - __bfloat162float(h));
    }
}

// ---------------- fused gate+up int8 kernel ----------------
// CTA 128x64, 256 thr (8 warps, 4x2), warp tile 32x32, K-chunk 128 int8.
// Stage: A1@0(16K) A0@16K G1@32K(8K) G0@40K U1@48K U0@56K.
__global__ void __launch_bounds__(256) fused_gateup_kernel(){
    int z = blockIdx.z, cnt, base;
    if (z == E_EXP){ cnt = N_TOK; base = 2*N_TOK; }
    else           { cnt = g_counts[z]; base = g_offsets[z]; }
    int rb = blockIdx.y;
    if (rb*128 >= cnt) return;
    int n0 = blockIdx.x * 64;

    extern __shared__ char smem[];
    uint32_t sb = (smem_u32(smem) + 1023u) & ~1023u;
    int tid = threadIdx.x, lane = tid & 31, wid = tid >> 5;
    int warp_m = wid >> 1, warp_n = wid & 1;

    const signed char* lsrc[2]; uint32_t ltoff[2]; int lrow[2];
    #pragma unroll
    for (int j = 0; j < 2; j++){
        int q = tid + j*256;
        int tile, row;
        if (q < 256){ tile = q >> 7; row = q & 127; }
        else        { tile = 2 + ((q - 256) >> 6); row = (q - 256) & 63; }
        const uint32_t offs[6] = {0u, 16384u, 32768u, 40960u, 49152u, 57344u};
        const signed char* p;
        if (tile < 2){
            int r = rb*128 + row; int rr = r < cnt ? r : cnt - 1;
            int tok = g_ids[base + rr];
            p = (tile == 0 ? g_x1 : g_x0) + (size_t)tok*C_DIM;
        } else {
            size_t wr = ((size_t)z*I_DIM + n0 + row)*C_DIM;
            const signed char* w = tile==2 ? g_wg1 : tile==3 ? g_wg0 : tile==4 ? g_wu1 : g_wu0;
            p = w + wr;
        }
        lsrc[j] = p; ltoff[j] = offs[tile]; lrow[j] = row;
    }
    auto load_stage = [&](int s, int kt){
        uint32_t st = sb + (uint32_t)s*STAGE_FI;
        #pragma unroll
        for (int j = 0; j < 2; j++)
            cp_row(st + ltoff[j], lsrc[j] + kt*128, lrow[j]);
        cp_commit();
    };

    int mat = lane >> 3;
    uint32_t xm = (uint32_t)(lane & 7) << 4;
    uint32_t rA[2], rB[2];
    #pragma unroll
    for (int mt = 0; mt < 2; mt++)
        rA[mt] = (uint32_t)(warp_m*32 + mt*16 + (mat & 1)*8 + (lane & 7)) << 7;
    #pragma unroll
    for (int p = 0; p < 2; p++)
        rB[p] = (uint32_t)(warp_n*32 + p*16 + ((mat >> 1) & 1)*8 + (lane & 7)) << 7;
    uint32_t caK = (uint32_t)((mat >> 1) & 1) * 16;
    uint32_t cbK = (uint32_t)(mat & 1) * 16;

    int g11[2][4][4], gx[2][4][4], u11[2][4][4], ux[2][4][4];
    #pragma unroll
    for (int a = 0; a < 2; a++)
        #pragma unroll
        for (int b = 0; b < 4; b++)
            #pragma unroll
            for (int c = 0; c < 4; c++){ g11[a][b][c]=0; gx[a][b][c]=0; u11[a][b][c]=0; ux[a][b][c]=0; }

    const int KT = C_DIM/128;   // 6
    load_stage(0, 0);
    load_stage(1, 1);

    for (int kt = 0; kt < KT; kt++){
        if (kt + 1 < KT) cp_wait1(); else cp_wait0();
        __syncthreads();
        uint32_t st = sb + (uint32_t)(kt & 1)*STAGE_FI;
        uint32_t A1s = st, A0s = st + 16384u;
        uint32_t G1s = st + 32768u, G0s = st + 40960u;
        uint32_t U1s = st + 49152u, U0s = st + 57344u;
        #pragma unroll
        for (int ks = 0; ks < 4; ks++){
            uint32_t cA = ((uint32_t)ks*32 + caK) ^ xm;
            uint32_t cB = ((uint32_t)ks*32 + cbK) ^ xm;
            uint32_t a1[2][4], a0[2][4];
            ldsm4(a1[0], A1s + rA[0] + cA); ldsm4(a1[1], A1s + rA[1] + cA);
            ldsm4(a0[0], A0s + rA[0] + cA); ldsm4(a0[1], A0s + rA[1] + cA);
            uint32_t bh[2][4], bl[2][4];
            // gate
            ldsm4(bh[0], G1s + rB[0] + cB); ldsm4(bh[1], G1s + rB[1] + cB);
            ldsm4(bl[0], G0s + rB[0] + cB); ldsm4(bl[1], G0s + rB[1] + cB);
            #pragma unroll
            for (int mt = 0; mt < 2; mt++)
                #pragma unroll
                for (int nt = 0; nt < 4; nt++)
                    imma(g11[mt][nt], a1[mt], bh[nt>>1][(nt&1)*2], bh[nt>>1][(nt&1)*2+1]);
            #pragma unroll
            for (int mt = 0; mt < 2; mt++)
                #pragma unroll
                for (int nt = 0; nt < 4; nt++)
                    imma(gx[mt][nt], a1[mt], bl[nt>>1][(nt&1)*2], bl[nt>>1][(nt&1)*2+1]);
            #pragma unroll
            for (int mt = 0; mt < 2; mt++)
                #pragma unroll
                for (int nt = 0; nt < 4; nt++)
                    imma(gx[mt][nt], a0[mt], bh[nt>>1][(nt&1)*2], bh[nt>>1][(nt&1)*2+1]);
            // up
            ldsm4(bh[0], U1s + rB[0] + cB); ldsm4(bh[1], U1s + rB[1] + cB);
            ldsm4(bl[0], U0s + rB[0] + cB); ldsm4(bl[1], U0s + rB[1] + cB);
            #pragma unroll
            for (int mt = 0; mt < 2; mt++)
                #pragma unroll
                for (int nt = 0; nt < 4; nt++)
                    imma(u11[mt][nt], a1[mt], bh[nt>>1][(nt&1)*2], bh[nt>>1][(nt&1)*2+1]);
            #pragma unroll
            for (int mt = 0; mt < 2; mt++)
                #pragma unroll
                for (int nt = 0; nt < 4; nt++)
                    imma(ux[mt][nt], a1[mt], bl[nt>>1][(nt&1)*2], bl[nt>>1][(nt&1)*2+1]);
            #pragma unroll
            for (int mt = 0; mt < 2; mt++)
                #pragma unroll
                for (int nt = 0; nt < 4; nt++)
                    imma(ux[mt][nt], a0[mt], bh[nt>>1][(nt&1)*2], bh[nt>>1][(nt&1)*2+1]);
        }
        __syncthreads();
        if (kt + 2 < KT) load_stage(kt & 1, kt + 2);
    }

    // epilogue: dequant, h = silu(g)*u -> bf16 hi/lo planes (R7-style)
    int qr = lane >> 2, qc = (lane & 3)*2;
    #pragma unroll
    for (int mt = 0; mt < 2; mt++)
        #pragma unroll
        for (int h2 = 0; h2 < 2; h2++){
            int gr = rb*128 + warp_m*32 + mt*16 + h2*8 + qr;
            if (gr >= cnt) continue;
            size_t slot = (size_t)base + gr;
            float sxv = g_sx[g_ids[slot]];
            #pragma unroll
            for (int nt = 0; nt < 4; nt++){
                int col = n0 + warp_n*32 + nt*8 + qc;
                float2 sgv = *(const float2*)(g_sg + z*I_DIM + col);
                float2 suv = *(const float2*)(g_su + z*I_DIM + col);
                float gv0 = sxv*sgv.x*((float)g11[mt][nt][h2*2+0] + (float)gx[mt][nt][h2*2+0]*(1.f/128.f));
                float gv1 = sxv*sgv.y*((float)g11[mt][nt][h2*2+1] + (float)gx[mt][nt][h2*2+1]*(1.f/128.f));
                float uv0 = sxv*suv.x*((float)u11[mt][nt][h2*2+0] + (float)ux[mt][nt][h2*2+0]*(1.f/128.f));
                float uv1 = sxv*suv.y*((float)u11[mt][nt][h2*2+1] + (float)ux[mt][nt][h2*2+1]*(1.f/128.f));
                float h0 = (gv0 / (1.f + __expf(-gv0))) * uv0;
                float h1 = (gv1 / (1.f + __expf(-gv1))) * uv1;
                __nv_bfloat16 h0h = __float2bfloat16(h0), h1h = __float2bfloat16(h1);
                __nv_bfloat162 vh; vh.x = h0h; vh.y = h1h;
                __nv_bfloat162 vl;
                vl.x = __float2bfloat16(h0 - __bfloat162float(h0h));
                vl.y = __float2bfloat16(h1 - __bfloat162float(h1h));
                *(__nv_bfloat162*)(g_hh + slot*I_DIM + col) = vh;
                *(__nv_bfloat162*)(g_hl + slot*I_DIM + col) = vl;
            }
        }
}

// ---------------- down-projection bf16 HMMA kernel (proven R8 code) ----------------
__global__ void __launch_bounds__(512) down_proj_kernel(){
    int z = blockIdx.z, cnt, base;
    if (z == E_EXP){ cnt = N_TOK; base = 2*N_TOK; }
    else           { cnt = g_counts[z]; base = g_offsets[z]; }
    int rb = blockIdx.y;
    if (rb*128 >= cnt) return;
    int n0 = blockIdx.x * 128;

    extern __shared__ char smem[];
    uint32_t sb = (smem_u32(smem) + 1023u) & ~1023u;
    int tid = threadIdx.x, lane = tid & 31, wid = tid >> 5;
    int warp_m = wid >> 2, warp_n = wid & 3;

    int ltile = tid >> 7, lrow = tid & 127;
    const char* lsrc;
    if (ltile < 2){
        int r = rb*128 + lrow; int rr = r < cnt ? r : cnt - 1;
        lsrc = (const char*)((ltile == 0 ? g_hh : g_hl) + (size_t)(base + rr)*I_DIM);
    } else {
        size_t wr = ((size_t)z*C_DIM + n0 + lrow)*I_DIM;
        lsrc = (const char*)((ltile == 2 ? g_dh : g_dl) + wr);
    }
    uint32_t ltoff = (uint32_t)ltile*TILE_B;
    auto load_stage = [&](int s, int kt){
        uint32_t st = sb + (uint32_t)s*STAGE_D;
        cp_row(st + ltoff, lsrc + kt*128, lrow);
        cp_commit();
    };

    int mat = lane >> 3;
    uint32_t xm = (uint32_t)(lane & 7) << 4;
    uint32_t rA[2], rB[2];
    #pragma unroll
    for (int mt = 0; mt < 2; mt++)
        rA[mt] = (uint32_t)(warp_m*32 + mt*16 + (mat & 1)*8 + (lane & 7)) << 7;
    #pragma unroll
    for (int p = 0; p < 2; p++)
        rB[p] = (uint32_t)(warp_n*32 + p*16 + ((mat >> 1) & 1)*8 + (lane & 7)) << 7;
    uint32_t caK = (uint32_t)((mat >> 1) & 1) * 16;
    uint32_t cbK = (uint32_t)(mat & 1) * 16;

    float ac[2][4][4];
    #pragma unroll
    for (int a = 0; a < 2; a++)
        #pragma unroll
        for (int b = 0; b < 4; b++)
            #pragma unroll
            for (int c = 0; c < 4; c++) ac[a][b][c] = 0.f;

    const int KT = I_DIM/64;   // 24
    load_stage(0, 0);
    load_stage(1, 1);

    for (int kt = 0; kt < KT; kt++){
        if (kt + 1 < KT) cp_wait1(); else cp_wait0();
        __syncthreads();
        uint32_t st = sb + (uint32_t)(kt & 1)*STAGE_D;
        uint32_t Ah = st, Al = st + TILE_B;
        uint32_t Bh = st + 2*TILE_B, Bl = st + 3*TILE_B;
        #pragma unroll
        for (int ks = 0; ks < 4; ks++){
            uint32_t cA = ((uint32_t)ks*32 + caK) ^ xm;
            uint32_t cB = ((uint32_t)ks*32 + cbK) ^ xm;
            uint32_t fah[2][4], fal[2][4];
            ldsm4(fah[0], Ah + rA[0] + cA); ldsm4(fah[1], Ah + rA[1] + cA);
            ldsm4(fal[0], Al + rA[0] + cA); ldsm4(fal[1], Al + rA[1] + cA);
            uint32_t b0[2][4], b1[2][4];
            ldsm4(b0[0], Bh + rB[0] + cB); ldsm4(b0[1], Bh + rB[1] + cB);
            ldsm4(b1[0], Bl + rB[0] + cB); ldsm4(b1[1], Bl + rB[1] + cB);
            #pragma unroll
            for (int mt = 0; mt < 2; mt++)
                #pragma unroll
                for (int nt = 0; nt < 4; nt++)
                    hmma(ac[mt][nt], fah[mt], &b0[nt>>1][(nt&1)*2]);
            #pragma unroll
            for (int mt = 0; mt < 2; mt++)
                #pragma unroll
                for (int nt = 0; nt < 4; nt++)
                    hmma(ac[mt][nt], fah[mt], &b1[nt>>1][(nt&1)*2]);
            #pragma unroll
            for (int mt = 0; mt < 2; mt++)
                #pragma unroll
                for (int nt = 0; nt < 4; nt++)
                    hmma(ac[mt][nt], fal[mt], &b0[nt>>1][(nt&1)*2]);
        }
        __syncthreads();
        if (kt + 2 < KT) load_stage(kt & 1, kt + 2);
    }

    int qr = lane >> 2, qc = (lane & 3)*2;
    #pragma unroll
    for (int mt = 0; mt < 2; mt++)
        #pragma unroll
        for (int h2 = 0; h2 < 2; h2++){
            int gr = rb*128 + warp_m*32 + mt*16 + h2*8 + qr;
            if (gr >= cnt) continue;
            size_t slot = (size_t)base + gr;
            float wt = g_wt[slot];
            #pragma unroll
            for (int nt = 0; nt < 4; nt++){
                float2 v;
                v.x = wt * ac[mt][nt][h2*2+0];
                v.y = wt * ac[mt][nt][h2*2+1];
                size_t col = (size_t)n0 + warp_n*32 + nt*8 + qc;
                *(float2*)(g_O + slot*C_DIM + col) = v;
            }
        }
}

__global__ void combine_kernel(float* __restrict__ out){
    int i = blockIdx.x * blockDim.x + threadIdx.x;
    if (i >= N_TOK*(C_DIM/4)) return;
    int t = i / (C_DIM/4), c = (i % (C_DIM/4)) * 4;
    int s0 = g_slot_of[t*2], s1 = g_slot_of[t*2+1];
    float4 a = *(const float4*)&g_O[(size_t)s0*C_DIM + c];
    float4 b = *(const float4*)&g_O[(size_t)s1*C_DIM + c];
    float4 d = *(const float4*)&g_O[(size_t)(2*N_TOK + t)*C_DIM + c];
    float4 r = make_float4(a.x+b.x+d.x, a.y+b.y+d.y, a.z+b.z+d.z, a.w+b.w+d.w);
    *(float4*)&out[(size_t)t*C_DIM + c] = r;
}

// ---------------- launch ----------------
extern "C" void kernel_launch(void* const* d_in, const int* in_sizes, int n_in,
                              void* d_out, int out_size) {
    const float* x    = (const float*)d_in[0];
    const float* wgt  = (const float*)d_in[1];
    const float* bias = (const float*)d_in[2];
    const float* wg   = (const float*)d_in[3];
    const float* wu   = (const float*)d_in[4];
    const float* wd   = (const float*)d_in[5];
    const float* swg  = (const float*)d_in[6];
    const float* swu  = (const float*)d_in[7];
    const float* swd  = (const float*)d_in[8];
    float* out = (float*)d_out;

    cudaFuncSetAttribute(fused_gateup_kernel, cudaFuncAttributeMaxDynamicSharedMemorySize, SMEM_FI);
    cudaFuncSetAttribute(down_proj_kernel,    cudaFuncAttributeMaxDynamicSharedMemorySize, SMEM_D);

    init_kernel<<<1, 32>>>();
    router_kernel<<<(N_TOK*32 + 255)/256, 256>>>(x, wgt, bias);
    scan_kernel<<<1, 1>>>();
    fill_kernel<<<(N_TOK + 255)/256, 256>>>();

    rowmax_x_kernel<<<(N_TOK*32 + 255)/256, 256>>>(x);
    quant_x_kernel<<<(N_TOK*C_DIM/4 + 255)/256, 256>>>(x);

    colmax_w_kernel<<<dim3(I_DIM/128, 1, E_EXP), 128>>>(wg,  0, 0,  C_DIM, I_DIM);
    colmax_w_kernel<<<dim3(I_DIM/128, 1, 1),     128>>>(swg, 0, 16, C_DIM, I_DIM);
    colmax_w_kernel<<<dim3(I_DIM/128, 1, E_EXP), 128>>>(wu,  1, 0,  C_DIM, I_DIM);
    colmax_w_kernel<<<dim3(I_DIM/128, 1, 1),     128>>>(swu, 1, 16, C_DIM, I_DIM);

    dim3 tb(32, 8);
    quantT_w_kernel<<<dim3(I_DIM/32, C_DIM/32, E_EXP), tb>>>(wg,  0, 0,  C_DIM, I_DIM);
    quantT_w_kernel<<<dim3(I_DIM/32, C_DIM/32, 1),     tb>>>(swg, 0, 16, C_DIM, I_DIM);
    quantT_w_kernel<<<dim3(I_DIM/32, C_DIM/32, E_EXP), tb>>>(wu,  1, 0,  C_DIM, I_DIM);
    quantT_w_kernel<<<dim3(I_DIM/32, C_DIM/32, 1),     tb>>>(swu, 1, 16, C_DIM, I_DIM);

    split_T_wd_kernel<<<dim3(C_DIM/32, I_DIM/32, E_EXP), tb>>>(wd,  0,  I_DIM, C_DIM);
    split_T_wd_kernel<<<dim3(C_DIM/32, I_DIM/32, 1),     tb>>>(swd, 16, I_DIM, C_DIM);

    fused_gateup_kernel<<<dim3(I_DIM/64, N_TOK/128, E_ALL), 256, SMEM_FI>>>();
    down_proj_kernel  <<<dim3(C_DIM/128, N_TOK/128, E_ALL), 512, SMEM_D>>>();
    combine_kernel<<<(N_TOK*(C_DIM/4) + 255)/256, 256>>>(out);
}

// round 12
// speedup vs baseline: 2.4638x; 2.4638x over previous
#include <cuda_runtime.h>
#include <cuda_fp16.h>
#include <math.h>
#include <stdint.h>

#define N_TOK 16384
#define C_DIM 768
#define I_DIM 1536
#define E_EXP 16
#define E_ALL 17
#define SLOTS (3*N_TOK)
#define TILE_B 16384
#define STAGE_F (4*TILE_B)
#define STAGE_D (3*TILE_B)
#define SMEM_F (2*STAGE_F + 1024)
#define SMEM_D (2*STAGE_D + 1024)

// ---------------- static device scratch ----------------
__device__ int   g_counts[E_EXP];
__device__ int   g_offsets[E_EXP];
__device__ int   g_cursor[E_EXP];
__device__ int   g_re[N_TOK*2];
__device__ float g_rw[N_TOK*2];
__device__ int   g_ids[SLOTS];
__device__ float g_wt[SLOTS];
__device__ int   g_slot_of[N_TOK*2];

__device__ __half g_xh[(size_t)N_TOK*C_DIM];
__device__ __half g_xl[(size_t)N_TOK*C_DIM];
__device__ __half g_wg[(size_t)E_ALL*I_DIM*C_DIM];   // [(e*I+n)*C+k] single plane
__device__ __half g_wu[(size_t)E_ALL*I_DIM*C_DIM];
__device__ __half g_wd[(size_t)E_ALL*C_DIM*I_DIM];   // [(e*C+n)*I+k]
__device__ __half g_hh[(size_t)SLOTS*I_DIM];
__device__ __half g_hl[(size_t)SLOTS*I_DIM];
__device__ float g_O[(size_t)SLOTS*C_DIM];

// ---------------- PTX helpers (base ISA only) ----------------
__device__ __forceinline__ uint32_t smem_u32(const void* p){
    uint32_t a;
    asm("{ .reg .u64 t; cvta.to.shared.u64 t, %1; cvt.u32.u64 %0, t; }" : "=r"(a) : "l"(p));
    return a;
}
__device__ __forceinline__ void cp_row(uint32_t sbase, const void* src, int t){
    #pragma unroll
    for (int ch = 0; ch < 8; ch++){
        uint32_t off = (uint32_t)t*128u + (uint32_t)ch*16u;
        uint32_t dst = sbase + (off ^ ((off >> 3) & 0x70u));
        asm volatile("cp.async.cg.shared.global [%0], [%1], 16;"
            :: "r"(dst), "l"((const char*)src + ch*16) : "memory");
    }
}
__device__ __forceinline__ void cp_commit(){ asm volatile("cp.async.commit_group;" ::: "memory"); }
__device__ __forceinline__ void cp_wait1(){ asm volatile("cp.async.wait_group 1;" ::: "memory"); }
__device__ __forceinline__ void cp_wait0(){ asm volatile("cp.async.wait_group 0;" ::: "memory"); }

__device__ __forceinline__ void ldsm4(uint32_t* r, uint32_t addr){
    asm volatile("ldmatrix.sync.aligned.m8n8.x4.shared.b16 {%0,%1,%2,%3}, [%4];"
        : "=r"(r[0]), "=r"(r[1]), "=r"(r[2]), "=r"(r[3]) : "r"(addr));
}
__device__ __forceinline__ void hmma(float* d, const uint32_t* a, const uint32_t* b){
    asm volatile("mma.sync.aligned.m16n8k16.row.col.f32.f16.f16.f32 "
        "{%0,%1,%2,%3}, {%4,%5,%6,%7}, {%8,%9}, {%0,%1,%2,%3};"
        : "+f"(d[0]), "+f"(d[1]), "+f"(d[2]), "+f"(d[3])
        : "r"(a[0]), "r"(a[1]), "r"(a[2]), "r"(a[3]), "r"(b[0]), "r"(b[1]));
}

// ---------------- routing setup ----------------
__global__ void init_kernel(){ if (threadIdx.x < E_EXP) g_counts[threadIdx.x] = 0; }

__global__ void router_kernel(const float* __restrict__ x, const float* __restrict__ wgate,
                              const float* __restrict__ bias){
    int warp = (blockIdx.x * blockDim.x + threadIdx.x) >> 5;
    int lane = threadIdx.x & 31;
    if (warp >= N_TOK) return;
    float acc = 0.f;
    if (lane < E_EXP){
        const float* xr = x + (size_t)warp * C_DIM;
        #pragma unroll 8
        for (int c = 0; c < C_DIM; c++) acc = fmaf(xr[c], wgate[c*E_EXP + lane], acc);
        acc += bias[lane];
    }
    float l0 = -1e30f, l1 = -1e30f; int i0 = 0, i1 = 0;
    #pragma unroll
    for (int e = 0; e < E_EXP; e++){
        float v = __shfl_sync(0xffffffffu, acc, e);
        if (v > l0)      { l1 = l0; i1 = i0; l0 = v; i0 = e; }
        else if (v > l1) { l1 = v;  i1 = e; }
    }
    if (lane == 0){
        float w0 = 1.f / (1.f + __expf(l1 - l0));
        g_re[warp*2+0] = i0; g_rw[warp*2+0] = w0;
        g_re[warp*2+1] = i1; g_rw[warp*2+1] = 1.f - w0;
        atomicAdd(&g_counts[i0], 1); atomicAdd(&g_counts[i1], 1);
    }
}

__global__ void scan_kernel(){
    if (threadIdx.x == 0){
        int off = 0;
        for (int e = 0; e < E_EXP; e++){ g_offsets[e] = off; g_cursor[e] = off; off += g_counts[e]; }
    }
}

__global__ void fill_kernel(){
    int t = blockIdx.x * blockDim.x + threadIdx.x;
    if (t >= N_TOK) return;
    #pragma unroll
    for (int s = 0; s < 2; s++){
        int e = g_re[t*2+s];
        int pos = atomicAdd(&g_cursor[e], 1);
        g_ids[pos] = t; g_wt[pos] = g_rw[t*2+s]; g_slot_of[t*2+s] = pos;
    }
    g_ids[2*N_TOK + t] = t; g_wt[2*N_TOK + t] = 1.f;
}

// ---------------- conversions ----------------
// x -> exact fp16 hi/lo pair
__global__ void split_x_kernel(const float* __restrict__ x){
    size_t i = (size_t)blockIdx.x * blockDim.x + threadIdx.x;
    if (i >= (size_t)N_TOK*C_DIM) return;
    float v = x[i];
    __half h = __float2half(v);
    g_xh[i] = h; g_xl[i] = __float2half(v - __half2float(h));
}

// weights: single fp16 plane, transposed. Output selected DEVICE-SIDE via which
// (0=wg, 1=wu, 2=wd) — never pass __device__ symbols as kernel args (R9/R10 bug).
__global__ void convT_w_kernel(const float* __restrict__ W, int which, int ebase, int K, int N){
    __shared__ float t[32][33];
    __half* outp = (which == 0) ? g_wg : (which == 1) ? g_wu : g_wd;
    int e = ebase + blockIdx.z;
    const float* Win = W + (size_t)blockIdx.z * K * N;
    int n0 = blockIdx.x*32, k0 = blockIdx.y*32;
    int tx = threadIdx.x, ty = threadIdx.y;   // (32,8)
    #pragma unroll
    for (int i = 0; i < 4; i++)
        t[ty + i*8][tx] = Win[(size_t)(k0 + ty + i*8)*N + n0 + tx];
    __syncthreads();
    #pragma unroll
    for (int i = 0; i < 4; i++){
        int n = n0 + ty + i*8;
        size_t o = ((size_t)e*N + n)*K + k0 + tx;
        outp[o] = __float2half(t[tx][ty + i*8]);
    }
}

// ---------------- fused gate+up fp16 kernel ----------------
// CTA 128x128, 512 thr (16 warps, 4x4, warp tile 32x32), K-chunk 64 halfs (128B).
// Stage tiles: Ah@0 Al@16K G@32K U@48K. 2-product: ah*b + al*b.
__global__ void __launch_bounds__(512) fused_gateup_kernel(){
    int z = blockIdx.z, cnt, base;
    if (z == E_EXP){ cnt = N_TOK; base = 2*N_TOK; }
    else           { cnt = g_counts[z]; base = g_offsets[z]; }
    int rb = blockIdx.y;
    if (rb*128 >= cnt) return;
    int n0 = blockIdx.x * 128;

    extern __shared__ char smem[];
    uint32_t sb = (smem_u32(smem) + 1023u) & ~1023u;
    int tid = threadIdx.x, lane = tid & 31, wid = tid >> 5;
    int warp_m = wid >> 2, warp_n = wid & 3;

    // loader: 4 tiles x 128 rows = 512 rows over 512 threads (exactly 1 each)
    int ltile = tid >> 7, lrow = tid & 127;
    const char* lsrc;
    if (ltile < 2){
        int r = rb*128 + lrow; int rr = r < cnt ? r : cnt - 1;
        int tok = g_ids[base + rr];
        lsrc = (const char*)((ltile == 0 ? g_xh : g_xl) + (size_t)tok*C_DIM);
    } else {
        size_t wr = ((size_t)z*I_DIM + n0 + lrow)*C_DIM;
        lsrc = (const char*)((ltile == 2 ? g_wg : g_wu) + wr);
    }
    uint32_t ltoff = (uint32_t)ltile*TILE_B;
    auto load_stage = [&](int s, int kt){
        uint32_t st = sb + (uint32_t)s*STAGE_F;
        cp_row(st + ltoff, lsrc + kt*128, lrow);
        cp_commit();
    };

    int mat = lane >> 3;
    uint32_t xm = (uint32_t)(lane & 7) << 4;
    uint32_t rA[2], rB[2];
    #pragma unroll
    for (int mt = 0; mt < 2; mt++)
        rA[mt] = (uint32_t)(warp_m*32 + mt*16 + (mat & 1)*8 + (lane & 7)) << 7;
    #pragma unroll
    for (int p = 0; p < 2; p++)
        rB[p] = (uint32_t)(warp_n*32 + p*16 + ((mat >> 1) & 1)*8 + (lane & 7)) << 7;
    uint32_t caK = (uint32_t)((mat >> 1) & 1) * 16;
    uint32_t cbK = (uint32_t)(mat & 1) * 16;

    float ag[2][4][4], au[2][4][4];
    #pragma unroll
    for (int a = 0; a < 2; a++)
        #pragma unroll
        for (int b = 0; b < 4; b++)
            #pragma unroll
            for (int c = 0; c < 4; c++){ ag[a][b][c] = 0.f; au[a][b][c] = 0.f; }

    const int KT = C_DIM/64;   // 12
    load_stage(0, 0);
    load_stage(1, 1);

    for (int kt = 0; kt < KT; kt++){
        if (kt + 1 < KT) cp_wait1(); else cp_wait0();
        __syncthreads();
        uint32_t st = sb + (uint32_t)(kt & 1)*STAGE_F;
        uint32_t Ah = st, Al = st + TILE_B;
        uint32_t Gt = st + 2*TILE_B, Ut = st + 3*TILE_B;
        #pragma unroll
        for (int ks = 0; ks < 4; ks++){
            uint32_t cA = ((uint32_t)ks*32 + caK) ^ xm;
            uint32_t cB = ((uint32_t)ks*32 + cbK) ^ xm;
            uint32_t ah[2][4], al[2][4];
            ldsm4(ah[0], Ah + rA[0] + cA); ldsm4(ah[1], Ah + rA[1] + cA);
            ldsm4(al[0], Al + rA[0] + cA); ldsm4(al[1], Al + rA[1] + cA);
            uint32_t bg[2][4], bu[2][4];
            ldsm4(bg[0], Gt + rB[0] + cB); ldsm4(bg[1], Gt + rB[1] + cB);
            ldsm4(bu[0], Ut + rB[0] + cB); ldsm4(bu[1], Ut + rB[1] + cB);
            // gate: ah*g then al*g
            #pragma unroll
            for (int mt = 0; mt < 2; mt++)
                #pragma unroll
                for (int nt = 0; nt < 4; nt++)
                    hmma(ag[mt][nt], ah[mt], &bg[nt>>1][(nt&1)*2]);
            #pragma unroll
            for (int mt = 0; mt < 2; mt++)
                #pragma unroll
                for (int nt = 0; nt < 4; nt++)
                    hmma(ag[mt][nt], al[mt], &bg[nt>>1][(nt&1)*2]);
            // up: ah*u then al*u
            #pragma unroll
            for (int mt = 0; mt < 2; mt++)
                #pragma unroll
                for (int nt = 0; nt < 4; nt++)
                    hmma(au[mt][nt], ah[mt], &bu[nt>>1][(nt&1)*2]);
            #pragma unroll
            for (int mt = 0; mt < 2; mt++)
                #pragma unroll
                for (int nt = 0; nt < 4; nt++)
                    hmma(au[mt][nt], al[mt], &bu[nt>>1][(nt&1)*2]);
        }
        __syncthreads();
        if (kt + 2 < KT) load_stage(kt & 1, kt + 2);
    }

    // epilogue: h = silu(g)*u -> fp16 hi/lo planes
    int qr = lane >> 2, qc = (lane & 3)*2;
    #pragma unroll
    for (int mt = 0; mt < 2; mt++)
        #pragma unroll
        for (int h2 = 0; h2 < 2; h2++){
            int gr = rb*128 + warp_m*32 + mt*16 + h2*8 + qr;
            if (gr >= cnt) continue;
            size_t slot = (size_t)base + gr;
            #pragma unroll
            for (int nt = 0; nt < 4; nt++){
                float g0 = ag[mt][nt][h2*2+0], g1 = ag[mt][nt][h2*2+1];
                float u0 = au[mt][nt][h2*2+0], u1 = au[mt][nt][h2*2+1];
                float h0 = (g0 / (1.f + __expf(-g0))) * u0;
                float h1 = (g1 / (1.f + __expf(-g1))) * u1;
                __half h0h = __float2half(h0), h1h = __float2half(h1);
                __half2 vh; vh.x = h0h; vh.y = h1h;
                __half2 vl;
                vl.x = __float2half(h0 - __half2float(h0h));
                vl.y = __float2half(h1 - __half2float(h1h));
                size_t col = (size_t)n0 + warp_n*32 + nt*8 + qc;
                *(__half2*)(g_hh + slot*I_DIM + col) = vh;
                *(__half2*)(g_hl + slot*I_DIM + col) = vl;
            }
        }
}

// ---------------- down-projection fp16 kernel ----------------
// CTA 128x128, 512 thr. Stage tiles: Hh@0 Hl@16K D@32K. 2-product.
__global__ void __launch_bounds__(512) down_proj_kernel(){
    int z = blockIdx.z, cnt, base;
    if (z == E_EXP){ cnt = N_TOK; base = 2*N_TOK; }
    else           { cnt = g_counts[z]; base = g_offsets[z]; }
    int rb = blockIdx.y;
    if (rb*128 >= cnt) return;
    int n0 = blockIdx.x * 128;

    extern __shared__ char smem[];
    uint32_t sb = (smem_u32(smem) + 1023u) & ~1023u;
    int tid = threadIdx.x, lane = tid & 31, wid = tid >> 5;
    int warp_m = wid >> 2, warp_n = wid & 3;

    // loader: 3 tiles x 128 rows = 384 rows; threads 384..511 idle
    int ltile = tid >> 7, lrow = tid & 127;
    bool lval = tid < 384;
    const char* lsrc = (const char*)g_hh;
    if (lval){
        if (ltile < 2){
            int r = rb*128 + lrow; int rr = r < cnt ? r : cnt - 1;
            lsrc = (const char*)((ltile == 0 ? g_hh : g_hl) + (size_t)(base + rr)*I_DIM);
        } else {
            size_t wr = ((size_t)z*C_DIM + n0 + lrow)*I_DIM;
            lsrc = (const char*)(g_wd + wr);
        }
    }
    uint32_t ltoff = (uint32_t)ltile*TILE_B;
    auto load_stage = [&](int s, int kt){
        uint32_t st = sb + (uint32_t)s*STAGE_D;
        if (lval) cp_row(st + ltoff, lsrc + kt*128, lrow);
        cp_commit();
    };

    int mat = lane >> 3;
    uint32_t xm = (uint32_t)(lane & 7) << 4;
    uint32_t rA[2], rB[2];
    #pragma unroll
    for (int mt = 0; mt < 2; mt++)
        rA[mt] = (uint32_t)(warp_m*32 + mt*16 + (mat & 1)*8 + (lane & 7)) << 7;
    #pragma unroll
    for (int p = 0; p < 2; p++)
        rB[p] = (uint32_t)(warp_n*32 + p*16 + ((mat >> 1) & 1)*8 + (lane & 7)) << 7;
    uint32_t caK = (uint32_t)((mat >> 1) & 1) * 16;
    uint32_t cbK = (uint32_t)(mat & 1) * 16;

    float ac[2][4][4];
    #pragma unroll
    for (int a = 0; a < 2; a++)
        #pragma unroll
        for (int b = 0; b < 4; b++)
            #pragma unroll
            for (int c = 0; c < 4; c++) ac[a][b][c] = 0.f;

    const int KT = I_DIM/64;   // 24
    load_stage(0, 0);
    load_stage(1, 1);

    for (int kt = 0; kt < KT; kt++){
        if (kt + 1 < KT) cp_wait1(); else cp_wait0();
        __syncthreads();
        uint32_t st = sb + (uint32_t)(kt & 1)*STAGE_D;
        uint32_t Ah = st, Al = st + TILE_B, Bt = st + 2*TILE_B;
        #pragma unroll
        for (int ks = 0; ks < 4; ks++){
            uint32_t cA = ((uint32_t)ks*32 + caK) ^ xm;
            uint32_t cB = ((uint32_t)ks*32 + cbK) ^ xm;
            uint32_t ah[2][4], al[2][4];
            ldsm4(ah[0], Ah + rA[0] + cA); ldsm4(ah[1], Ah + rA[1] + cA);
            ldsm4(al[0], Al + rA[0] + cA); ldsm4(al[1], Al + rA[1] + cA);
            uint32_t bd[2][4];
            ldsm4(bd[0], Bt + rB[0] + cB); ldsm4(bd[1], Bt + rB[1] + cB);
            #pragma unroll
            for (int mt = 0; mt < 2; mt++)
                #pragma unroll
                for (int nt = 0; nt < 4; nt++)
                    hmma(ac[mt][nt], ah[mt], &bd[nt>>1][(nt&1)*2]);
            #pragma unroll
            for (int mt = 0; mt < 2; mt++)
                #pragma unroll
                for (int nt = 0; nt < 4; nt++)
                    hmma(ac[mt][nt], al[mt], &bd[nt>>1][(nt&1)*2]);
        }
        __syncthreads();
        if (kt + 2 < KT) load_stage(kt & 1, kt + 2);
    }

    int qr = lane >> 2, qc = (lane & 3)*2;
    #pragma unroll
    for (int mt = 0; mt < 2; mt++)
        #pragma unroll
        for (int h2 = 0; h2 < 2; h2++){
            int gr = rb*128 + warp_m*32 + mt*16 + h2*8 + qr;
            if (gr >= cnt) continue;
            size_t slot = (size_t)base + gr;
            float wt = g_wt[slot];
            #pragma unroll
            for (int nt = 0; nt < 4; nt++){
                float2 v;
                v.x = wt * ac[mt][nt][h2*2+0];
                v.y = wt * ac[mt][nt][h2*2+1];
                size_t col = (size_t)n0 + warp_n*32 + nt*8 + qc;
                *(float2*)(g_O + slot*C_DIM + col) = v;
            }
        }
}

__global__ void combine_kernel(float* __restrict__ out){
    int i = blockIdx.x * blockDim.x + threadIdx.x;
    if (i >= N_TOK*(C_DIM/4)) return;
    int t = i / (C_DIM/4), c = (i % (C_DIM/4)) * 4;
    int s0 = g_slot_of[t*2], s1 = g_slot_of[t*2+1];
    float4 a = *(const float4*)&g_O[(size_t)s0*C_DIM + c];
    float4 b = *(const float4*)&g_O[(size_t)s1*C_DIM + c];
    float4 d = *(const float4*)&g_O[(size_t)(2*N_TOK + t)*C_DIM + c];
    float4 r = make_float4(a.x+b.x+d.x, a.y+b.y+d.y, a.z+b.z+d.z, a.w+b.w+d.w);
    *(float4*)&out[(size_t)t*C_DIM + c] = r;
}

// ---------------- launch ----------------
extern "C" void kernel_launch(void* const* d_in, const int* in_sizes, int n_in,
                              void* d_out, int out_size) {
    const float* x    = (const float*)d_in[0];
    const float* wgt  = (const float*)d_in[1];
    const float* bias = (const float*)d_in[2];
    const float* wg   = (const float*)d_in[3];
    const float* wu   = (const float*)d_in[4];
    const float* wd   = (const float*)d_in[5];
    const float* swg  = (const float*)d_in[6];
    const float* swu  = (const float*)d_in[7];
    const float* swd  = (const float*)d_in[8];
    float* out = (float*)d_out;

    cudaFuncSetAttribute(fused_gateup_kernel, cudaFuncAttributeMaxDynamicSharedMemorySize, SMEM_F);
    cudaFuncSetAttribute(down_proj_kernel,    cudaFuncAttributeMaxDynamicSharedMemorySize, SMEM_D);

    init_kernel<<<1, 32>>>();
    router_kernel<<<(N_TOK*32 + 255)/256, 256>>>(x, wgt, bias);
    scan_kernel<<<1, 1>>>();
    fill_kernel<<<(N_TOK + 255)/256, 256>>>();

    split_x_kernel<<<(N_TOK*C_DIM + 255)/256, 256>>>(x);
    dim3 tb(32, 8);
    convT_w_kernel<<<dim3(I_DIM/32, C_DIM/32, E_EXP), tb>>>(wg,  0, 0,  C_DIM, I_DIM);
    convT_w_kernel<<<dim3(I_DIM/32, C_DIM/32, 1),     tb>>>(swg, 0, 16, C_DIM, I_DIM);
    convT_w_kernel<<<dim3(I_DIM/32, C_DIM/32, E_EXP), tb>>>(wu,  1, 0,  C_DIM, I_DIM);
    convT_w_kernel<<<dim3(I_DIM/32, C_DIM/32, 1),     tb>>>(swu, 1, 16, C_DIM, I_DIM);
    convT_w_kernel<<<dim3(C_DIM/32, I_DIM/32, E_EXP), tb>>>(wd,  2, 0,  I_DIM, C_DIM);
    convT_w_kernel<<<dim3(C_DIM/32, I_DIM/32, 1),     tb>>>(swd, 2, 16, I_DIM, C_DIM);

    fused_gateup_kernel<<<dim3(I_DIM/128, N_TOK/128, E_ALL), 512, SMEM_F>>>();
    down_proj_kernel  <<<dim3(C_DIM/128, N_TOK/128, E_ALL), 512, SMEM_D>>>();
    combine_kernel<<<(N_TOK*(C_DIM/4) + 255)/256, 256>>>(out);
}

// round 13
// speedup vs baseline: 2.9620x; 1.2022x over previous
#include <cuda_runtime.h>
#include <cuda_fp16.h>
#include <math.h>
#include <stdint.h>

#define N_TOK 16384
#define C_DIM 768
#define I_DIM 1536
#define E_EXP 16
#define E_ALL 17
#define SLOTS (3*N_TOK)
#define TILE_B 16384
#define STAGE_F (4*TILE_B)
#define STAGE_D (2*TILE_B)
#define SMEM_F (2*STAGE_F + 1024)
#define SMEM_D (2*STAGE_D + 1024)

// ---------------- static device scratch ----------------
__device__ int   g_counts[E_EXP];
__device__ int   g_offsets[E_EXP];
__device__ int   g_cursor[E_EXP];
__device__ int   g_re[N_TOK*2];
__device__ float g_rw[N_TOK*2];
__device__ int   g_ids[SLOTS];
__device__ float g_wt[SLOTS];
__device__ int   g_slot_of[N_TOK*2];

__device__ __half g_xh[(size_t)N_TOK*C_DIM];
__device__ __half g_xl[(size_t)N_TOK*C_DIM];
__device__ __half g_wg[(size_t)E_ALL*I_DIM*C_DIM];   // [(e*I+n)*C+k] single plane
__device__ __half g_wu[(size_t)E_ALL*I_DIM*C_DIM];
__device__ __half g_wd[(size_t)E_ALL*C_DIM*I_DIM];   // [(e*C+n)*I+k]
__device__ __half g_hh[(size_t)SLOTS*I_DIM];         // H single fp16 plane
__device__ float g_O[(size_t)SLOTS*C_DIM];

// ---------------- PTX helpers (base ISA only) ----------------
__device__ __forceinline__ uint32_t smem_u32(const void* p){
    uint32_t a;
    asm("{ .reg .u64 t; cvta.to.shared.u64 t, %1; cvt.u32.u64 %0, t; }" : "=r"(a) : "l"(p));
    return a;
}
__device__ __forceinline__ void cp_row(uint32_t sbase, const void* src, int t){
    #pragma unroll
    for (int ch = 0; ch < 8; ch++){
        uint32_t off = (uint32_t)t*128u + (uint32_t)ch*16u;
        uint32_t dst = sbase + (off ^ ((off >> 3) & 0x70u));
        asm volatile("cp.async.cg.shared.global [%0], [%1], 16;"
            :: "r"(dst), "l"((const char*)src + ch*16) : "memory");
    }
}
__device__ __forceinline__ void cp_commit(){ asm volatile("cp.async.commit_group;" ::: "memory"); }
__device__ __forceinline__ void cp_wait1(){ asm volatile("cp.async.wait_group 1;" ::: "memory"); }
__device__ __forceinline__ void cp_wait0(){ asm volatile("cp.async.wait_group 0;" ::: "memory"); }

__device__ __forceinline__ void ldsm4(uint32_t* r, uint32_t addr){
    asm volatile("ldmatrix.sync.aligned.m8n8.x4.shared.b16 {%0,%1,%2,%3}, [%4];"
        : "=r"(r[0]), "=r"(r[1]), "=r"(r[2]), "=r"(r[3]) : "r"(addr));
}
__device__ __forceinline__ void hmma(float* d, const uint32_t* a, const uint32_t* b){
    asm volatile("mma.sync.aligned.m16n8k16.row.col.f32.f16.f16.f32 "
        "{%0,%1,%2,%3}, {%4,%5,%6,%7}, {%8,%9}, {%0,%1,%2,%3};"
        : "+f"(d[0]), "+f"(d[1]), "+f"(d[2]), "+f"(d[3])
        : "r"(a[0]), "r"(a[1]), "r"(a[2]), "r"(a[3]), "r"(b[0]), "r"(b[1]));
}

// ---------------- routing setup ----------------
__global__ void init_kernel(){ if (threadIdx.x < E_EXP) g_counts[threadIdx.x] = 0; }

__global__ void router_kernel(const float* __restrict__ x, const float* __restrict__ wgate,
                              const float* __restrict__ bias){
    int warp = (blockIdx.x * blockDim.x + threadIdx.x) >> 5;
    int lane = threadIdx.x & 31;
    if (warp >= N_TOK) return;
    float acc = 0.f;
    if (lane < E_EXP){
        const float* xr = x + (size_t)warp * C_DIM;
        #pragma unroll 8
        for (int c = 0; c < C_DIM; c++) acc = fmaf(xr[c], wgate[c*E_EXP + lane], acc);
        acc += bias[lane];
    }
    float l0 = -1e30f, l1 = -1e30f; int i0 = 0, i1 = 0;
    #pragma unroll
    for (int e = 0; e < E_EXP; e++){
        float v = __shfl_sync(0xffffffffu, acc, e);
        if (v > l0)      { l1 = l0; i1 = i0; l0 = v; i0 = e; }
        else if (v > l1) { l1 = v;  i1 = e; }
    }
    if (lane == 0){
        float w0 = 1.f / (1.f + __expf(l1 - l0));
        g_re[warp*2+0] = i0; g_rw[warp*2+0] = w0;
        g_re[warp*2+1] = i1; g_rw[warp*2+1] = 1.f - w0;
        atomicAdd(&g_counts[i0], 1); atomicAdd(&g_counts[i1], 1);
    }
}

__global__ void scan_kernel(){
    if (threadIdx.x == 0){
        int off = 0;
        for (int e = 0; e < E_EXP; e++){ g_offsets[e] = off; g_cursor[e] = off; off += g_counts[e]; }
    }
}

__global__ void fill_kernel(){
    int t = blockIdx.x * blockDim.x + threadIdx.x;
    if (t >= N_TOK) return;
    #pragma unroll
    for (int s = 0; s < 2; s++){
        int e = g_re[t*2+s];
        int pos = atomicAdd(&g_cursor[e], 1);
        g_ids[pos] = t; g_wt[pos] = g_rw[t*2+s]; g_slot_of[t*2+s] = pos;
    }
    g_ids[2*N_TOK + t] = t; g_wt[2*N_TOK + t] = 1.f;
}

// ---------------- conversions ----------------
// x -> exact fp16 hi/lo pair
__global__ void split_x_kernel(const float* __restrict__ x){
    size_t i = (size_t)blockIdx.x * blockDim.x + threadIdx.x;
    if (i >= (size_t)N_TOK*C_DIM) return;
    float v = x[i];
    __half h = __float2half(v);
    g_xh[i] = h; g_xl[i] = __float2half(v - __half2float(h));
}

// weights: single fp16 plane, transposed. Output selected DEVICE-SIDE via which
// (0=wg, 1=wu, 2=wd) — never pass __device__ symbols as kernel args (R9/R10 bug).
__global__ void convT_w_kernel(const float* __restrict__ W, int which, int ebase, int K, int N){
    __shared__ float t[32][33];
    __half* outp = (which == 0) ? g_wg : (which == 1) ? g_wu : g_wd;
    int e = ebase + blockIdx.z;
    const float* Win = W + (size_t)blockIdx.z * K * N;
    int n0 = blockIdx.x*32, k0 = blockIdx.y*32;
    int tx = threadIdx.x, ty = threadIdx.y;   // (32,8)
    #pragma unroll
    for (int i = 0; i < 4; i++)
        t[ty + i*8][tx] = Win[(size_t)(k0 + ty + i*8)*N + n0 + tx];
    __syncthreads();
    #pragma unroll
    for (int i = 0; i < 4; i++){
        int n = n0 + ty + i*8;
        size_t o = ((size_t)e*N + n)*K + k0 + tx;
        outp[o] = __float2half(t[tx][ty + i*8]);
    }
}

// ---------------- fused gate+up fp16 kernel ----------------
// CTA 128x128, 512 thr (16 warps, 4x4, warp tile 32x32), K-chunk 64 halfs (128B).
// Stage tiles: Ah@0 Al@16K G@32K U@48K. 2-product: ah*b + al*b.
__global__ void __launch_bounds__(512) fused_gateup_kernel(){
    int z = blockIdx.z, cnt, base;
    if (z == E_EXP){ cnt = N_TOK; base = 2*N_TOK; }
    else           { cnt = g_counts[z]; base = g_offsets[z]; }
    int rb = blockIdx.y;
    if (rb*128 >= cnt) return;
    int n0 = blockIdx.x * 128;

    extern __shared__ char smem[];
    uint32_t sb = (smem_u32(smem) + 1023u) & ~1023u;
    int tid = threadIdx.x, lane = tid & 31, wid = tid >> 5;
    int warp_m = wid >> 2, warp_n = wid & 3;

    // loader: 4 tiles x 128 rows = 512 rows over 512 threads (exactly 1 each)
    int ltile = tid >> 7, lrow = tid & 127;
    const char* lsrc;
    if (ltile < 2){
        int r = rb*128 + lrow; int rr = r < cnt ? r : cnt - 1;
        int tok = g_ids[base + rr];
        lsrc = (const char*)((ltile == 0 ? g_xh : g_xl) + (size_t)tok*C_DIM);
    } else {
        size_t wr = ((size_t)z*I_DIM + n0 + lrow)*C_DIM;
        lsrc = (const char*)((ltile == 2 ? g_wg : g_wu) + wr);
    }
    uint32_t ltoff = (uint32_t)ltile*TILE_B;
    auto load_stage = [&](int s, int kt){
        uint32_t st = sb + (uint32_t)s*STAGE_F;
        cp_row(st + ltoff, lsrc + kt*128, lrow);
        cp_commit();
    };

    int mat = lane >> 3;
    uint32_t xm = (uint32_t)(lane & 7) << 4;
    uint32_t rA[2], rB[2];
    #pragma unroll
    for (int mt = 0; mt < 2; mt++)
        rA[mt] = (uint32_t)(warp_m*32 + mt*16 + (mat & 1)*8 + (lane & 7)) << 7;
    #pragma unroll
    for (int p = 0; p < 2; p++)
        rB[p] = (uint32_t)(warp_n*32 + p*16 + ((mat >> 1) & 1)*8 + (lane & 7)) << 7;
    uint32_t caK = (uint32_t)((mat >> 1) & 1) * 16;
    uint32_t cbK = (uint32_t)(mat & 1) * 16;

    float ag[2][4][4], au[2][4][4];
    #pragma unroll
    for (int a = 0; a < 2; a++)
        #pragma unroll
        for (int b = 0; b < 4; b++)
            #pragma unroll
            for (int c = 0; c < 4; c++){ ag[a][b][c] = 0.f; au[a][b][c] = 0.f; }

    const int KT = C_DIM/64;   // 12
    load_stage(0, 0);
    load_stage(1, 1);

    for (int kt = 0; kt < KT; kt++){
        if (kt + 1 < KT) cp_wait1(); else cp_wait0();
        __syncthreads();
        uint32_t st = sb + (uint32_t)(kt & 1)*STAGE_F;
        uint32_t Ah = st, Al = st + TILE_B;
        uint32_t Gt = st + 2*TILE_B, Ut = st + 3*TILE_B;
        #pragma unroll
        for (int ks = 0; ks < 4; ks++){
            uint32_t cA = ((uint32_t)ks*32 + caK) ^ xm;
            uint32_t cB = ((uint32_t)ks*32 + cbK) ^ xm;
            uint32_t ah[2][4], al[2][4];
            ldsm4(ah[0], Ah + rA[0] + cA); ldsm4(ah[1], Ah + rA[1] + cA);
            ldsm4(al[0], Al + rA[0] + cA); ldsm4(al[1], Al + rA[1] + cA);
            uint32_t bg[2][4], bu[2][4];
            ldsm4(bg[0], Gt + rB[0] + cB); ldsm4(bg[1], Gt + rB[1] + cB);
            ldsm4(bu[0], Ut + rB[0] + cB); ldsm4(bu[1], Ut + rB[1] + cB);
            // gate: ah*g then al*g
            #pragma unroll
            for (int mt = 0; mt < 2; mt++)
                #pragma unroll
                for (int nt = 0; nt < 4; nt++)
                    hmma(ag[mt][nt], ah[mt], &bg[nt>>1][(nt&1)*2]);
            #pragma unroll
            for (int mt = 0; mt < 2; mt++)
                #pragma unroll
                for (int nt = 0; nt < 4; nt++)
                    hmma(ag[mt][nt], al[mt], &bg[nt>>1][(nt&1)*2]);
            // up: ah*u then al*u
            #pragma unroll
            for (int mt = 0; mt < 2; mt++)
                #pragma unroll
                for (int nt = 0; nt < 4; nt++)
                    hmma(au[mt][nt], ah[mt], &bu[nt>>1][(nt&1)*2]);
            #pragma unroll
            for (int mt = 0; mt < 2; mt++)
                #pragma unroll
                for (int nt = 0; nt < 4; nt++)
                    hmma(au[mt][nt], al[mt], &bu[nt>>1][(nt&1)*2]);
        }
        __syncthreads();
        if (kt + 2 < KT) load_stage(kt & 1, kt + 2);
    }

    // epilogue: h = silu(g)*u -> single fp16 plane
    int qr = lane >> 2, qc = (lane & 3)*2;
    #pragma unroll
    for (int mt = 0; mt < 2; mt++)
        #pragma unroll
        for (int h2 = 0; h2 < 2; h2++){
            int gr = rb*128 + warp_m*32 + mt*16 + h2*8 + qr;
            if (gr >= cnt) continue;
            size_t slot = (size_t)base + gr;
            #pragma unroll
            for (int nt = 0; nt < 4; nt++){
                float g0 = ag[mt][nt][h2*2+0], g1 = ag[mt][nt][h2*2+1];
                float u0 = au[mt][nt][h2*2+0], u1 = au[mt][nt][h2*2+1];
                float h0 = (g0 / (1.f + __expf(-g0))) * u0;
                float h1 = (g1 / (1.f + __expf(-g1))) * u1;
                __half2 vh; vh.x = __float2half(h0); vh.y = __float2half(h1);
                size_t col = (size_t)n0 + warp_n*32 + nt*8 + qc;
                *(__half2*)(g_hh + slot*I_DIM + col) = vh;
            }
        }
}

// ---------------- down-projection fp16 kernel (single product) ----------------
// CTA 128x128, 512 thr. Stage tiles: H@0 D@16K. 1 product: h*d.
__global__ void __launch_bounds__(512) down_proj_kernel(){
    int z = blockIdx.z, cnt, base;
    if (z == E_EXP){ cnt = N_TOK; base = 2*N_TOK; }
    else           { cnt = g_counts[z]; base = g_offsets[z]; }
    int rb = blockIdx.y;
    if (rb*128 >= cnt) return;
    int n0 = blockIdx.x * 128;

    extern __shared__ char smem[];
    uint32_t sb = (smem_u32(smem) + 1023u) & ~1023u;
    int tid = threadIdx.x, lane = tid & 31, wid = tid >> 5;
    int warp_m = wid >> 2, warp_n = wid & 3;

    // loader: 2 tiles x 128 rows = 256 rows; threads 256..511 idle
    int ltile = tid >> 7, lrow = tid & 127;
    bool lval = tid < 256;
    const char* lsrc = (const char*)g_hh;
    if (lval){
        if (ltile == 0){
            int r = rb*128 + lrow; int rr = r < cnt ? r : cnt - 1;
            lsrc = (const char*)(g_hh + (size_t)(base + rr)*I_DIM);
        } else {
            size_t wr = ((size_t)z*C_DIM + n0 + lrow)*I_DIM;
            lsrc = (const char*)(g_wd + wr);
        }
    }
    uint32_t ltoff = (uint32_t)ltile*TILE_B;
    auto load_stage = [&](int s, int kt){
        uint32_t st = sb + (uint32_t)s*STAGE_D;
        if (lval) cp_row(st + ltoff, lsrc + kt*128, lrow);
        cp_commit();
    };

    int mat = lane >> 3;
    uint32_t xm = (uint32_t)(lane & 7) << 4;
    uint32_t rA[2], rB[2];
    #pragma unroll
    for (int mt = 0; mt < 2; mt++)
        rA[mt] = (uint32_t)(warp_m*32 + mt*16 + (mat & 1)*8 + (lane & 7)) << 7;
    #pragma unroll
    for (int p = 0; p < 2; p++)
        rB[p] = (uint32_t)(warp_n*32 + p*16 + ((mat >> 1) & 1)*8 + (lane & 7)) << 7;
    uint32_t caK = (uint32_t)((mat >> 1) & 1) * 16;
    uint32_t cbK = (uint32_t)(mat & 1) * 16;

    float ac[2][4][4];
    #pragma unroll
    for (int a = 0; a < 2; a++)
        #pragma unroll
        for (int b = 0; b < 4; b++)
            #pragma unroll
            for (int c = 0; c < 4; c++) ac[a][b][c] = 0.f;

    const int KT = I_DIM/64;   // 24
    load_stage(0, 0);
    load_stage(1, 1);

    for (int kt = 0; kt < KT; kt++){
        if (kt + 1 < KT) cp_wait1(); else cp_wait0();
        __syncthreads();
        uint32_t st = sb + (uint32_t)(kt & 1)*STAGE_D;
        uint32_t Ht = st, Dt = st + TILE_B;
        #pragma unroll
        for (int ks = 0; ks < 4; ks++){
            uint32_t cA = ((uint32_t)ks*32 + caK) ^ xm;
            uint32_t cB = ((uint32_t)ks*32 + cbK) ^ xm;
            uint32_t ah[2][4];
            ldsm4(ah[0], Ht + rA[0] + cA); ldsm4(ah[1], Ht + rA[1] + cA);
            uint32_t bd[2][4];
            ldsm4(bd[0], Dt + rB[0] + cB); ldsm4(bd[1], Dt + rB[1] + cB);
            #pragma unroll
            for (int mt = 0; mt < 2; mt++)
                #pragma unroll
                for (int nt = 0; nt < 4; nt++)
                    hmma(ac[mt][nt], ah[mt], &bd[nt>>1][(nt&1)*2]);
        }
        __syncthreads();
        if (kt + 2 < KT) load_stage(kt & 1, kt + 2);
    }

    int qr = lane >> 2, qc = (lane & 3)*2;
    #pragma unroll
    for (int mt = 0; mt < 2; mt++)
        #pragma unroll
        for (int h2 = 0; h2 < 2; h2++){
            int gr = rb*128 + warp_m*32 + mt*16 + h2*8 + qr;
            if (gr >= cnt) continue;
            size_t slot = (size_t)base + gr;
            float wt = g_wt[slot];
            #pragma unroll
            for (int nt = 0; nt < 4; nt++){
                float2 v;
                v.x = wt * ac[mt][nt][h2*2+0];
                v.y = wt * ac[mt][nt][h2*2+1];
                size_t col = (size_t)n0 + warp_n*32 + nt*8 + qc;
                *(float2*)(g_O + slot*C_DIM + col) = v;
            }
        }
}

__global__ void combine_kernel(float* __restrict__ out){
    int i = blockIdx.x * blockDim.x + threadIdx.x;
    if (i >= N_TOK*(C_DIM/4)) return;
    int t = i / (C_DIM/4), c = (i % (C_DIM/4)) * 4;
    int s0 = g_slot_of[t*2], s1 = g_slot_of[t*2+1];
    float4 a = *(const float4*)&g_O[(size_t)s0*C_DIM + c];
    float4 b = *(const float4*)&g_O[(size_t)s1*C_DIM + c];
    float4 d = *(const float4*)&g_O[(size_t)(2*N_TOK + t)*C_DIM + c];
    float4 r = make_float4(a.x+b.x+d.x, a.y+b.y+d.y, a.z+b.z+d.z, a.w+b.w+d.w);
    *(float4*)&out[(size_t)t*C_DIM + c] = r;
}

// ---------------- launch ----------------
extern "C" void kernel_launch(void* const* d_in, const int* in_sizes, int n_in,
                              void* d_out, int out_size) {
    const float* x    = (const float*)d_in[0];
    const float* wgt  = (const float*)d_in[1];
    const float* bias = (const float*)d_in[2];
    const float* wg   = (const float*)d_in[3];
    const float* wu   = (const float*)d_in[4];
    const float* wd   = (const float*)d_in[5];
    const float* swg  = (const float*)d_in[6];
    const float* swu  = (const float*)d_in[7];
    const float* swd  = (const float*)d_in[8];
    float* out = (float*)d_out;

    cudaFuncSetAttribute(fused_gateup_kernel, cudaFuncAttributeMaxDynamicSharedMemorySize, SMEM_F);
    cudaFuncSetAttribute(down_proj_kernel,    cudaFuncAttributeMaxDynamicSharedMemorySize, SMEM_D);

    init_kernel<<<1, 32>>>();
    router_kernel<<<(N_TOK*32 + 255)/256, 256>>>(x, wgt, bias);
    scan_kernel<<<1, 1>>>();
    fill_kernel<<<(N_TOK + 255)/256, 256>>>();

    split_x_kernel<<<(N_TOK*C_DIM + 255)/256, 256>>>(x);
    dim3 tb(32, 8);
    convT_w_kernel<<<dim3(I_DIM/32, C_DIM/32, E_EXP), tb>>>(wg,  0, 0,  C_DIM, I_DIM);
    convT_w_kernel<<<dim3(I_DIM/32, C_DIM/32, 1),     tb>>>(swg, 0, 16, C_DIM, I_DIM);
    convT_w_kernel<<<dim3(I_DIM/32, C_DIM/32, E_EXP), tb>>>(wu,  1, 0,  C_DIM, I_DIM);
    convT_w_kernel<<<dim3(I_DIM/32, C_DIM/32, 1),     tb>>>(swu, 1, 16, C_DIM, I_DIM);
    convT_w_kernel<<<dim3(C_DIM/32, I_DIM/32, E_EXP), tb>>>(wd,  2, 0,  I_DIM, C_DIM);
    convT_w_kernel<<<dim3(C_DIM/32, I_DIM/32, 1),     tb>>>(swd, 2, 16, I_DIM, C_DIM);

    fused_gateup_kernel<<<dim3(I_DIM/128, N_TOK/128, E_ALL), 512, SMEM_F>>>();
    down_proj_kernel  <<<dim3(C_DIM/128, N_TOK/128, E_ALL), 512, SMEM_D>>>();
    combine_kernel<<<(N_TOK*(C_DIM/4) + 255)/256, 256>>>(out);
}

// round 14
// speedup vs baseline: 3.8088x; 1.2859x over previous
#include <cuda_runtime.h>
#include <cuda_fp16.h>
#include <math.h>
#include <stdint.h>

#define N_TOK 16384
#define C_DIM 768
#define I_DIM 1536
#define E_EXP 16
#define E_ALL 17
#define SLOTS (3*N_TOK)
#define TILE_B 16384
#define STAGE_F (3*TILE_B)
#define STAGE_D (2*TILE_B)
#define SMEM_F (2*STAGE_F + 1024)
#define SMEM_D (2*STAGE_D + 1024)

// ---------------- static device scratch ----------------
__device__ int   g_counts[E_EXP];
__device__ int   g_offsets[E_EXP];
__device__ int   g_cursor[E_EXP];
__device__ int   g_re[N_TOK*2];
__device__ float g_rw[N_TOK*2];
__device__ int   g_ids[SLOTS];
__device__ float g_wt[SLOTS];
__device__ int   g_slot_of[N_TOK*2];

__device__ __half g_xh[(size_t)N_TOK*C_DIM];          // x single fp16 plane
__device__ __half g_wg[(size_t)E_ALL*I_DIM*C_DIM];    // [(e*I+n)*C+k]
__device__ __half g_wu[(size_t)E_ALL*I_DIM*C_DIM];
__device__ __half g_wd[(size_t)E_ALL*C_DIM*I_DIM];    // [(e*C+n)*I+k]
__device__ __half g_hh[(size_t)SLOTS*I_DIM];          // H single fp16 plane
__device__ float g_O[(size_t)SLOTS*C_DIM];

// ---------------- PTX helpers (base ISA only) ----------------
__device__ __forceinline__ uint32_t smem_u32(const void* p){
    uint32_t a;
    asm("{ .reg .u64 t; cvta.to.shared.u64 t, %1; cvt.u32.u64 %0, t; }" : "=r"(a) : "l"(p));
    return a;
}
__device__ __forceinline__ void cp_row(uint32_t sbase, const void* src, int t){
    #pragma unroll
    for (int ch = 0; ch < 8; ch++){
        uint32_t off = (uint32_t)t*128u + (uint32_t)ch*16u;
        uint32_t dst = sbase + (off ^ ((off >> 3) & 0x70u));
        asm volatile("cp.async.cg.shared.global [%0], [%1], 16;"
            :: "r"(dst), "l"((const char*)src + ch*16) : "memory");
    }
}
__device__ __forceinline__ void cp_commit(){ asm volatile("cp.async.commit_group;" ::: "memory"); }
__device__ __forceinline__ void cp_wait1(){ asm volatile("cp.async.wait_group 1;" ::: "memory"); }
__device__ __forceinline__ void cp_wait0(){ asm volatile("cp.async.wait_group 0;" ::: "memory"); }

__device__ __forceinline__ void ldsm4(uint32_t* r, uint32_t addr){
    asm volatile("ldmatrix.sync.aligned.m8n8.x4.shared.b16 {%0,%1,%2,%3}, [%4];"
        : "=r"(r[0]), "=r"(r[1]), "=r"(r[2]), "=r"(r[3]) : "r"(addr));
}
__device__ __forceinline__ void hmma(float* d, const uint32_t* a, const uint32_t* b){
    asm volatile("mma.sync.aligned.m16n8k16.row.col.f32.f16.f16.f32 "
        "{%0,%1,%2,%3}, {%4,%5,%6,%7}, {%8,%9}, {%0,%1,%2,%3};"
        : "+f"(d[0]), "+f"(d[1]), "+f"(d[2]), "+f"(d[3])
        : "r"(a[0]), "r"(a[1]), "r"(a[2]), "r"(a[3]), "r"(b[0]), "r"(b[1]));
}

// ---------------- routing setup ----------------
__global__ void init_kernel(){ if (threadIdx.x < E_EXP) g_counts[threadIdx.x] = 0; }

__global__ void router_kernel(const float* __restrict__ x, const float* __restrict__ wgate,
                              const float* __restrict__ bias){
    int warp = (blockIdx.x * blockDim.x + threadIdx.x) >> 5;
    int lane = threadIdx.x & 31;
    if (warp >= N_TOK) return;
    float acc = 0.f;
    if (lane < E_EXP){
        const float* xr = x + (size_t)warp * C_DIM;
        #pragma unroll 8
        for (int c = 0; c < C_DIM; c++) acc = fmaf(xr[c], wgate[c*E_EXP + lane], acc);
        acc += bias[lane];
    }
    float l0 = -1e30f, l1 = -1e30f; int i0 = 0, i1 = 0;
    #pragma unroll
    for (int e = 0; e < E_EXP; e++){
        float v = __shfl_sync(0xffffffffu, acc, e);
        if (v > l0)      { l1 = l0; i1 = i0; l0 = v; i0 = e; }
        else if (v > l1) { l1 = v;  i1 = e; }
    }
    if (lane == 0){
        float w0 = 1.f / (1.f + __expf(l1 - l0));
        g_re[warp*2+0] = i0; g_rw[warp*2+0] = w0;
        g_re[warp*2+1] = i1; g_rw[warp*2+1] = 1.f - w0;
        atomicAdd(&g_counts[i0], 1); atomicAdd(&g_counts[i1], 1);
    }
}

__global__ void scan_kernel(){
    if (threadIdx.x == 0){
        int off = 0;
        for (int e = 0; e < E_EXP; e++){ g_offsets[e] = off; g_cursor[e] = off; off += g_counts[e]; }
    }
}

__global__ void fill_kernel(){
    int t = blockIdx.x * blockDim.x + threadIdx.x;
    if (t >= N_TOK) return;
    #pragma unroll
    for (int s = 0; s < 2; s++){
        int e = g_re[t*2+s];
        int pos = atomicAdd(&g_cursor[e], 1);
        g_ids[pos] = t; g_wt[pos] = g_rw[t*2+s]; g_slot_of[t*2+s] = pos;
    }
    g_ids[2*N_TOK + t] = t; g_wt[2*N_TOK + t] = 1.f;
}

// ---------------- conversions ----------------
__global__ void conv_x_kernel(const float* __restrict__ x){
    size_t i = (size_t)blockIdx.x * blockDim.x + threadIdx.x;
    if (i >= (size_t)N_TOK*C_DIM) return;
    g_xh[i] = __float2half(x[i]);
}

// weights: single fp16 plane, transposed. Output selected DEVICE-SIDE via which
// (0=wg, 1=wu, 2=wd) — never pass __device__ symbols as kernel args (R9/R10 bug).
__global__ void convT_w_kernel(const float* __restrict__ W, int which, int ebase, int K, int N){
    __shared__ float t[32][33];
    __half* outp = (which == 0) ? g_wg : (which == 1) ? g_wu : g_wd;
    int e = ebase + blockIdx.z;
    const float* Win = W + (size_t)blockIdx.z * K * N;
    int n0 = blockIdx.x*32, k0 = blockIdx.y*32;
    int tx = threadIdx.x, ty = threadIdx.y;   // (32,8)
    #pragma unroll
    for (int i = 0; i < 4; i++)
        t[ty + i*8][tx] = Win[(size_t)(k0 + ty + i*8)*N + n0 + tx];
    __syncthreads();
    #pragma unroll
    for (int i = 0; i < 4; i++){
        int n = n0 + ty + i*8;
        size_t o = ((size_t)e*N + n)*K + k0 + tx;
        outp[o] = __float2half(t[tx][ty + i*8]);
    }
}

// ---------------- fused gate+up fp16 kernel (single product) ----------------
// CTA 128x128, 512 thr (16 warps, 4x4, warp tile 32x32), K-chunk 64 halfs (128B).
// Stage tiles: A@0 G@16K U@32K.
__global__ void __launch_bounds__(512) fused_gateup_kernel(){
    int z = blockIdx.z, cnt, base;
    if (z == E_EXP){ cnt = N_TOK; base = 2*N_TOK; }
    else           { cnt = g_counts[z]; base = g_offsets[z]; }
    int rb = blockIdx.y;
    if (rb*128 >= cnt) return;
    int n0 = blockIdx.x * 128;

    extern __shared__ char smem[];
    uint32_t sb = (smem_u32(smem) + 1023u) & ~1023u;
    int tid = threadIdx.x, lane = tid & 31, wid = tid >> 5;
    int warp_m = wid >> 2, warp_n = wid & 3;

    // loader: 3 tiles x 128 rows = 384 rows; threads 384..511 idle
    int ltile = tid >> 7, lrow = tid & 127;
    bool lval = tid < 384;
    const char* lsrc = (const char*)g_xh;
    if (lval){
        if (ltile == 0){
            int r = rb*128 + lrow; int rr = r < cnt ? r : cnt - 1;
            int tok = g_ids[base + rr];
            lsrc = (const char*)(g_xh + (size_t)tok*C_DIM);
        } else {
            size_t wr = ((size_t)z*I_DIM + n0 + lrow)*C_DIM;
            lsrc = (const char*)((ltile == 1 ? g_wg : g_wu) + wr);
        }
    }
    uint32_t ltoff = (uint32_t)ltile*TILE_B;
    auto load_stage = [&](int s, int kt){
        uint32_t st = sb + (uint32_t)s*STAGE_F;
        if (lval) cp_row(st + ltoff, lsrc + kt*128, lrow);
        cp_commit();
    };

    int mat = lane >> 3;
    uint32_t xm = (uint32_t)(lane & 7) << 4;
    uint32_t rA[2], rB[2];
    #pragma unroll
    for (int mt = 0; mt < 2; mt++)
        rA[mt] = (uint32_t)(warp_m*32 + mt*16 + (mat & 1)*8 + (lane & 7)) << 7;
    #pragma unroll
    for (int p = 0; p < 2; p++)
        rB[p] = (uint32_t)(warp_n*32 + p*16 + ((mat >> 1) & 1)*8 + (lane & 7)) << 7;
    uint32_t caK = (uint32_t)((mat >> 1) & 1) * 16;
    uint32_t cbK = (uint32_t)(mat & 1) * 16;

    float ag[2][4][4], au[2][4][4];
    #pragma unroll
    for (int a = 0; a < 2; a++)
        #pragma unroll
        for (int b = 0; b < 4; b++)
            #pragma unroll
            for (int c = 0; c < 4; c++){ ag[a][b][c] = 0.f; au[a][b][c] = 0.f; }

    const int KT = C_DIM/64;   // 12
    load_stage(0, 0);
    load_stage(1, 1);

    for (int kt = 0; kt < KT; kt++){
        if (kt + 1 < KT) cp_wait1(); else cp_wait0();
        __syncthreads();
        uint32_t st = sb + (uint32_t)(kt & 1)*STAGE_F;
        uint32_t At = st, Gt = st + TILE_B, Ut = st + 2*TILE_B;
        #pragma unroll
        for (int ks = 0; ks < 4; ks++){
            uint32_t cA = ((uint32_t)ks*32 + caK) ^ xm;
            uint32_t cB = ((uint32_t)ks*32 + cbK) ^ xm;
            uint32_t ah[2][4];
            ldsm4(ah[0], At + rA[0] + cA); ldsm4(ah[1], At + rA[1] + cA);
            uint32_t bg[2][4], bu[2][4];
            ldsm4(bg[0], Gt + rB[0] + cB); ldsm4(bg[1], Gt + rB[1] + cB);
            ldsm4(bu[0], Ut + rB[0] + cB); ldsm4(bu[1], Ut + rB[1] + cB);
            #pragma unroll
            for (int mt = 0; mt < 2; mt++)
                #pragma unroll
                for (int nt = 0; nt < 4; nt++)
                    hmma(ag[mt][nt], ah[mt], &bg[nt>>1][(nt&1)*2]);
            #pragma unroll
            for (int mt = 0; mt < 2; mt++)
                #pragma unroll
                for (int nt = 0; nt < 4; nt++)
                    hmma(au[mt][nt], ah[mt], &bu[nt>>1][(nt&1)*2]);
        }
        __syncthreads();
        if (kt + 2 < KT) load_stage(kt & 1, kt + 2);
    }

    // epilogue: h = silu(g)*u -> single fp16 plane
    int qr = lane >> 2, qc = (lane & 3)*2;
    #pragma unroll
    for (int mt = 0; mt < 2; mt++)
        #pragma unroll
        for (int h2 = 0; h2 < 2; h2++){
            int gr = rb*128 + warp_m*32 + mt*16 + h2*8 + qr;
            if (gr >= cnt) continue;
            size_t slot = (size_t)base + gr;
            #pragma unroll
            for (int nt = 0; nt < 4; nt++){
                float g0 = ag[mt][nt][h2*2+0], g1 = ag[mt][nt][h2*2+1];
                float u0 = au[mt][nt][h2*2+0], u1 = au[mt][nt][h2*2+1];
                float h0 = (g0 / (1.f + __expf(-g0))) * u0;
                float h1 = (g1 / (1.f + __expf(-g1))) * u1;
                __half2 vh; vh.x = __float2half(h0); vh.y = __float2half(h1);
                size_t col = (size_t)n0 + warp_n*32 + nt*8 + qc;
                *(__half2*)(g_hh + slot*I_DIM + col) = vh;
            }
        }
}

// ---------------- down-projection fp16 kernel (single product) ----------------
// CTA 128x128, 512 thr. Stage tiles: H@0 D@16K.
__global__ void __launch_bounds__(512) down_proj_kernel(){
    int z = blockIdx.z, cnt, base;
    if (z == E_EXP){ cnt = N_TOK; base = 2*N_TOK; }
    else           { cnt = g_counts[z]; base = g_offsets[z]; }
    int rb = blockIdx.y;
    if (rb*128 >= cnt) return;
    int n0 = blockIdx.x * 128;

    extern __shared__ char smem[];
    uint32_t sb = (smem_u32(smem) + 1023u) & ~1023u;
    int tid = threadIdx.x, lane = tid & 31, wid = tid >> 5;
    int warp_m = wid >> 2, warp_n = wid & 3;

    // loader: 2 tiles x 128 rows = 256 rows; threads 256..511 idle
    int ltile = tid >> 7, lrow = tid & 127;
    bool lval = tid < 256;
    const char* lsrc = (const char*)g_hh;
    if (lval){
        if (ltile == 0){
            int r = rb*128 + lrow; int rr = r < cnt ? r : cnt - 1;
            lsrc = (const char*)(g_hh + (size_t)(base + rr)*I_DIM);
        } else {
            size_t wr = ((size_t)z*C_DIM + n0 + lrow)*I_DIM;
            lsrc = (const char*)(g_wd + wr);
        }
    }
    uint32_t ltoff = (uint32_t)ltile*TILE_B;
    auto load_stage = [&](int s, int kt){
        uint32_t st = sb + (uint32_t)s*STAGE_D;
        if (lval) cp_row(st + ltoff, lsrc + kt*128, lrow);
        cp_commit();
    };

    int mat = lane >> 3;
    uint32_t xm = (uint32_t)(lane & 7) << 4;
    uint32_t rA[2], rB[2];
    #pragma unroll
    for (int mt = 0; mt < 2; mt++)
        rA[mt] = (uint32_t)(warp_m*32 + mt*16 + (mat & 1)*8 + (lane & 7)) << 7;
    #pragma unroll
    for (int p = 0; p < 2; p++)
        rB[p] = (uint32_t)(warp_n*32 + p*16 + ((mat >> 1) & 1)*8 + (lane & 7)) << 7;
    uint32_t caK = (uint32_t)((mat >> 1) & 1) * 16;
    uint32_t cbK = (uint32_t)(mat & 1) * 16;

    float ac[2][4][4];
    #pragma unroll
    for (int a = 0; a < 2; a++)
        #pragma unroll
        for (int b = 0; b < 4; b++)
            #pragma unroll
            for (int c = 0; c < 4; c++) ac[a][b][c] = 0.f;

    const int KT = I_DIM/64;   // 24
    load_stage(0, 0);
    load_stage(1, 1);

    for (int kt = 0; kt < KT; kt++){
        if (kt + 1 < KT) cp_wait1(); else cp_wait0();
        __syncthreads();
        uint32_t st = sb + (uint32_t)(kt & 1)*STAGE_D;
        uint32_t Ht = st, Dt = st + TILE_B;
        #pragma unroll
        for (int ks = 0; ks < 4; ks++){
            uint32_t cA = ((uint32_t)ks*32 + caK) ^ xm;
            uint32_t cB = ((uint32_t)ks*32 + cbK) ^ xm;
            uint32_t ah[2][4];
            ldsm4(ah[0], Ht + rA[0] + cA); ldsm4(ah[1], Ht + rA[1] + cA);
            uint32_t bd[2][4];
            ldsm4(bd[0], Dt + rB[0] + cB); ldsm4(bd[1], Dt + rB[1] + cB);
            #pragma unroll
            for (int mt = 0; mt < 2; mt++)
                #pragma unroll
                for (int nt = 0; nt < 4; nt++)
                    hmma(ac[mt][nt], ah[mt], &bd[nt>>1][(nt&1)*2]);
        }
        __syncthreads();
        if (kt + 2 < KT) load_stage(kt & 1, kt + 2);
    }

    int qr = lane >> 2, qc = (lane & 3)*2;
    #pragma unroll
    for (int mt = 0; mt < 2; mt++)
        #pragma unroll
        for (int h2 = 0; h2 < 2; h2++){
            int gr = rb*128 + warp_m*32 + mt*16 + h2*8 + qr;
            if (gr >= cnt) continue;
            size_t slot = (size_t)base + gr;
            float wt = g_wt[slot];
            #pragma unroll
            for (int nt = 0; nt < 4; nt++){
                float2 v;
                v.x = wt * ac[mt][nt][h2*2+0];
                v.y = wt * ac[mt][nt][h2*2+1];
                size_t col = (size_t)n0 + warp_n*32 + nt*8 + qc;
                *(float2*)(g_O + slot*C_DIM + col) = v;
            }
        }
}

__global__ void combine_kernel(float* __restrict__ out){
    int i = blockIdx.x * blockDim.x + threadIdx.x;
    if (i >= N_TOK*(C_DIM/4)) return;
    int t = i / (C_DIM/4), c = (i % (C_DIM/4)) * 4;
    int s0 = g_slot_of[t*2], s1 = g_slot_of[t*2+1];
    float4 a = *(const float4*)&g_O[(size_t)s0*C_DIM + c];
    float4 b = *(const float4*)&g_O[(size_t)s1*C_DIM + c];
    float4 d = *(const float4*)&g_O[(size_t)(2*N_TOK + t)*C_DIM + c];
    float4 r = make_float4(a.x+b.x+d.x, a.y+b.y+d.y, a.z+b.z+d.z, a.w+b.w+d.w);
    *(float4*)&out[(size_t)t*C_DIM + c] = r;
}

// ---------------- launch ----------------
extern "C" void kernel_launch(void* const* d_in, const int* in_sizes, int n_in,
                              void* d_out, int out_size) {
    const float* x    = (const float*)d_in[0];
    const float* wgt  = (const float*)d_in[1];
    const float* bias = (const float*)d_in[2];
    const float* wg   = (const float*)d_in[3];
    const float* wu   = (const float*)d_in[4];
    const float* wd   = (const float*)d_in[5];
    const float* swg  = (const float*)d_in[6];
    const float* swu  = (const float*)d_in[7];
    const float* swd  = (const float*)d_in[8];
    float* out = (float*)d_out;

    cudaFuncSetAttribute(fused_gateup_kernel, cudaFuncAttributeMaxDynamicSharedMemorySize, SMEM_F);
    cudaFuncSetAttribute(down_proj_kernel,    cudaFuncAttributeMaxDynamicSharedMemorySize, SMEM_D);

    init_kernel<<<1, 32>>>();
    router_kernel<<<(N_TOK*32 + 255)/256, 256>>>(x, wgt, bias);
    scan_kernel<<<1, 1>>>();
    fill_kernel<<<(N_TOK + 255)/256, 256>>>();

    conv_x_kernel<<<(N_TOK*C_DIM + 255)/256, 256>>>(x);
    dim3 tb(32, 8);
    convT_w_kernel<<<dim3(I_DIM/32, C_DIM/32, E_EXP), tb>>>(wg,  0, 0,  C_DIM, I_DIM);
    convT_w_kernel<<<dim3(I_DIM/32, C_DIM/32, 1),     tb>>>(swg, 0, 16, C_DIM, I_DIM);
    convT_w_kernel<<<dim3(I_DIM/32, C_DIM/32, E_EXP), tb>>>(wu,  1, 0,  C_DIM, I_DIM);
    convT_w_kernel<<<dim3(I_DIM/32, C_DIM/32, 1),     tb>>>(swu, 1, 16, C_DIM, I_DIM);
    convT_w_kernel<<<dim3(C_DIM/32, I_DIM/32, E_EXP), tb>>>(wd,  2, 0,  I_DIM, C_DIM);
    convT_w_kernel<<<dim3(C_DIM/32, I_DIM/32, 1),     tb>>>(swd, 2, 16, I_DIM, C_DIM);

    fused_gateup_kernel<<<dim3(I_DIM/128, N_TOK/128, E_ALL), 512, SMEM_F>>>();
    down_proj_kernel  <<<dim3(C_DIM/128, N_TOK/128, E_ALL), 512, SMEM_D>>>();
    combine_kernel<<<(N_TOK*(C_DIM/4) + 255)/256, 256>>>(out);
}